// round 10
// baseline (speedup 1.0000x reference)
#include <cuda_runtime.h>
#include <cuda_fp16.h>
#include <cstdint>

#define CDIM   2048
#define EDIM   64
#define NTOT   128          // 64 route + 64 noise outputs fused in N
#define TOPK   8
#define MT     128          // tokens per CTA
#define KC     64           // K per chunk (4 ks-steps of 16)
#define NCHUNK (CDIM / KC)  // 32
#define NTHR   512

// operand scaling to keep fp16 residuals out of subnormal range
#define XSCALE   16.0f
#define WSCALE   64.0f
#define DESCALE  (1.0f / (XSCALE * WSCALE))

// smem tile rows: 64 halves (128B) padded to 144B (conflict-free ldmatrix)
#define AROW        144
#define TILE_B      (128 * AROW)        // 18432 B per operand tile (A or B, hi or lo)
#define STAGE_B     (4 * TILE_B)        // Ahi, Alo, Bhi, Blo = 73728 B
#define SMEM_DYN    (2 * STAGE_B)       // 147456 B (reused as Ls in epilogue)
#define LS_STRIDE   129                 // 128*129*4 = 66048 B < STAGE_B (stage-0 only)

static __device__ __forceinline__ uint32_t smem_u32(const void* p) {
    uint32_t a;
    asm("{ .reg .u64 t; cvta.to.shared.u64 t, %1; cvt.u32.u64 %0, t; }" : "=r"(a) : "l"(p));
    return a;
}
static __device__ __forceinline__ void mbar_init(uint32_t a, uint32_t cnt) {
    asm volatile("mbarrier.init.shared.b64 [%0], %1;" :: "r"(a), "r"(cnt) : "memory");
}
static __device__ __forceinline__ void mbar_arrive(uint32_t a) {
    asm volatile("mbarrier.arrive.shared.b64 _, [%0];" :: "r"(a) : "memory");
}
static __device__ __forceinline__ void mbar_wait(uint32_t a, uint32_t parity) {
    asm volatile(
        "{\n\t.reg .pred P;\n\t"
        "W_%=:\n\t"
        "mbarrier.try_wait.parity.acquire.cta.shared::cta.b64 P, [%0], %1, 0x989680;\n\t"
        "@P bra.uni D_%=;\n\t"
        "bra.uni W_%=;\n\t"
        "D_%=:\n\t}"
        :: "r"(a), "r"(parity) : "memory");
}
static __device__ __forceinline__ void ldm_x4(uint32_t& r0, uint32_t& r1, uint32_t& r2,
                                              uint32_t& r3, uint32_t addr) {
    asm volatile("ldmatrix.sync.aligned.m8n8.x4.shared.b16 {%0,%1,%2,%3}, [%4];"
                 : "=r"(r0), "=r"(r1), "=r"(r2), "=r"(r3) : "r"(addr));
}
static __device__ __forceinline__ void mma16816(float* c, const uint32_t* a,
                                                const uint32_t* b) {
    asm volatile(
        "mma.sync.aligned.m16n8k16.row.col.f32.f16.f16.f32 "
        "{%0,%1,%2,%3}, {%4,%5,%6,%7}, {%8,%9}, {%0,%1,%2,%3};"
        : "+f"(c[0]), "+f"(c[1]), "+f"(c[2]), "+f"(c[3])
        : "r"(a[0]), "r"(a[1]), "r"(a[2]), "r"(a[3]), "r"(b[0]), "r"(b[1]));
}
static __device__ __forceinline__ uint32_t pack2h(__half a, __half b) {
    __half2 h = __halves2half2(a, b);
    return *reinterpret_cast<uint32_t*>(&h);
}
// Scale, then split into hi/lo fp16 quads and store 8B each.
static __device__ __forceinline__ void cvt_store(char* hi, char* lo, uint32_t off,
                                                 float4 v, float scale) {
    v.x *= scale; v.y *= scale; v.z *= scale; v.w *= scale;
    __half h0 = __float2half_rn(v.x), h1 = __float2half_rn(v.y);
    __half h2 = __float2half_rn(v.z), h3 = __float2half_rn(v.w);
    float r0 = v.x - __half2float(h0), r1 = v.y - __half2float(h1);
    float r2 = v.z - __half2float(h2), r3 = v.w - __half2float(h3);
    uint2 ph = make_uint2(pack2h(h0, h1), pack2h(h2, h3));
    uint2 pl = make_uint2(pack2h(__float2half_rn(r0), __float2half_rn(r1)),
                          pack2h(__float2half_rn(r2), __float2half_rn(r3)));
    *(uint2*)(hi + off) = ph;
    *(uint2*)(lo + off) = pl;
}

__global__ __launch_bounds__(NTHR, 1)
void router_mma_kernel(
    const float* __restrict__ x, const float* __restrict__ w_route,
    const float* __restrict__ w_noise, const float* __restrict__ noise,
    float* __restrict__ out_router, float* __restrict__ out_indices, int write_indices)
{
    extern __shared__ __align__(16) char smem[];
    __shared__ float s_max[MT];
    __shared__ float s_inv[MT];
    __shared__ unsigned long long s_msk[MT];
    __shared__ __align__(8) unsigned long long mbar_sto[2];   // FULL[0], FULL[1]

    const uint32_t sb = smem_u32(smem);
    const uint32_t mb = smem_u32(mbar_sto);
    const int tid = threadIdx.x;
    const int wid = tid >> 5, lane = tid & 31;
    const int wr_ = wid >> 2;            // warp row: tokens [32*wr_, +32)
    const int wc_ = wid & 3;             // warp col: outputs [32*wc_, +32)
    const int tokBase = blockIdx.x * MT;

    // fill mapping (per 32-k half): idx = tid + 512*it (it 0..1) -> row, q
    const int f_row = tid >> 3;          // 0..63 ; +64 for it=1
    const int f_q   = tid & 7;           // float4 slot within 32-k half

    // ldmatrix lane-address components
    const int j = lane >> 3, rr = lane & 7;
    const int a_off0 = (32 * wr_ + (j & 1) * 8 + rr) * AROW + (j >> 1) * 16;  // + mt*16*AROW + ks*32
    const int b_off0 = (32 * wc_ + (j >> 1) * 8 + rr) * AROW + (j & 1) * 16;  // + p*16*AROW + ks*32

    float acc[2][4][4];
#pragma unroll
    for (int mt = 0; mt < 2; ++mt)
#pragma unroll
        for (int nt = 0; nt < 4; ++nt)
#pragma unroll
            for (int k = 0; k < 4; ++k) acc[mt][nt][k] = 0.0f;

    // double-buffered hi fragments; lo fragments loaded just-in-time
    uint32_t ahi[2][2][4];   // [buf][mt][r]
    uint32_t bhi[2][4][2];   // [buf][nt][r]
    float4 areg[2], breg[2];

    auto ldg_half = [&](int kbase) {
#pragma unroll
        for (int it = 0; it < 2; ++it) {
            const int row = f_row + it * 64;
            areg[it] = *(const float4*)(x + (size_t)(tokBase + row) * CDIM + kbase + f_q * 4);
            const float* wsrc = (row < EDIM) ? (w_route + (size_t)row * CDIM)
                                             : (w_noise + (size_t)(row - EDIM) * CDIM);
            breg[it] = *(const float4*)(wsrc + kbase + f_q * 4);
        }
    };
    auto publish_half = [&](char* stage, int half) {
#pragma unroll
        for (int it = 0; it < 2; ++it) {
            const uint32_t off = (uint32_t)(f_row + it * 64) * AROW + half * 64 + f_q * 8;
            cvt_store(stage, stage + TILE_B, off, areg[it], XSCALE);
            cvt_store(stage + 2 * TILE_B, stage + 3 * TILE_B, off, breg[it], WSCALE);
        }
    };
    auto load_hi = [&](int buf, uint32_t ah_b, uint32_t bh_b, int ks) {
#pragma unroll
        for (int mt = 0; mt < 2; ++mt)
            ldm_x4(ahi[buf][mt][0], ahi[buf][mt][1], ahi[buf][mt][2], ahi[buf][mt][3],
                   ah_b + a_off0 + mt * (16 * AROW) + ks * 32);
#pragma unroll
        for (int p = 0; p < 2; ++p)
            ldm_x4(bhi[buf][2 * p][0], bhi[buf][2 * p][1], bhi[buf][2 * p + 1][0],
                   bhi[buf][2 * p + 1][1], bh_b + b_off0 + p * (16 * AROW) + ks * 32);
    };

    // ---- init barriers, fill stage 0 ----
    if (tid == 0) { mbar_init(mb, NTHR); mbar_init(mb + 8, NTHR); }
    ldg_half(0);
    __syncthreads();                       // covers mbar init
    publish_half(smem, 0);
    ldg_half(32);
    publish_half(smem, 1);
    mbar_arrive(mb);                       // FULL[0]
    int ph0 = 0, ph1 = 0;

    // ---- mainloop: 32 chunks, producer-consumer phases, no bar.sync ----
    for (int c = 0; c < NCHUNK; ++c) {
        const int s = c & 1;
        const int has_next = (c + 1 < NCHUNK);
        const uint32_t ah_b = sb + s * STAGE_B;
        const uint32_t al_b = ah_b + TILE_B;
        const uint32_t bh_b = ah_b + 2 * TILE_B;
        const uint32_t bl_b = ah_b + 3 * TILE_B;
        char* nstage = smem + (1 - s) * STAGE_B;

        if (has_next) ldg_half((c + 1) * KC);   // prefetch before the wait (extra MLP)

        // wait until stage s is fully published by all threads; this also
        // certifies every thread finished READING stage 1-s (arrive is after
        // both, in program order) -> safe to overwrite stage 1-s below.
        if (s == 0) { mbar_wait(mb, ph0 & 1); ph0++; }
        else        { mbar_wait(mb + 8, ph1 & 1); ph1++; }

        load_hi(0, ah_b, bh_b, 0);

#pragma unroll
        for (int ks = 0; ks < 4; ++ks) {
            const int cur = ks & 1;
            // just-in-time lo frags for this ks
            uint32_t alo[2][4], blo[4][2];
#pragma unroll
            for (int mt = 0; mt < 2; ++mt)
                ldm_x4(alo[mt][0], alo[mt][1], alo[mt][2], alo[mt][3],
                       al_b + a_off0 + mt * (16 * AROW) + ks * 32);
#pragma unroll
            for (int p = 0; p < 2; ++p)
                ldm_x4(blo[2 * p][0], blo[2 * p][1], blo[2 * p + 1][0], blo[2 * p + 1][1],
                       bl_b + b_off0 + p * (16 * AROW) + ks * 32);
            // preload hi frags of ks+1 while this ks' MMAs run
            if (ks < 3) load_hi(1 - cur, ah_b, bh_b, ks + 1);

            // MMAs grouped by term; per-acc order hihi->hilo->lohi (bitwise-stable)
#pragma unroll
            for (int mt = 0; mt < 2; ++mt)
#pragma unroll
                for (int nt = 0; nt < 4; ++nt)
                    mma16816(acc[mt][nt], ahi[cur][mt], bhi[cur][nt]);
#pragma unroll
            for (int mt = 0; mt < 2; ++mt)
#pragma unroll
                for (int nt = 0; nt < 4; ++nt)
                    mma16816(acc[mt][nt], ahi[cur][mt], blo[nt]);
#pragma unroll
            for (int mt = 0; mt < 2; ++mt)
#pragma unroll
                for (int nt = 0; nt < 4; ++nt)
                    mma16816(acc[mt][nt], alo[mt], bhi[cur][nt]);

            // mid-chunk: publish half0(c+1) into the other stage, fetch half1(c+1)
            if (ks == 1 && has_next) {
                publish_half(nstage, 0);
                ldg_half((c + 1) * KC + 32);
            }
        }

        if (has_next) {
            publish_half(nstage, 1);
            if (s == 0) mbar_arrive(mb + 8);   // FULL[1]
            else        mbar_arrive(mb);       // FULL[0]
        }
    }

    // --- accumulators -> Ls[token][output] (stage-0 region only; all threads
    // are past the FULL wait of the last chunk -> stage 0 reads are done) ---
    float* Ls = (float*)smem;
    {
        const int r0 = 32 * wr_ + (lane >> 2);
        const int c0 = 32 * wc_ + 2 * (lane & 3);
#pragma unroll
        for (int mt = 0; mt < 2; ++mt)
#pragma unroll
            for (int nt = 0; nt < 4; ++nt) {
                const int row = r0 + 16 * mt;
                const int col = c0 + 8 * nt;
                Ls[row * LS_STRIDE + col]           = acc[mt][nt][0] * DESCALE;
                Ls[row * LS_STRIDE + col + 1]       = acc[mt][nt][1] * DESCALE;
                Ls[(row + 8) * LS_STRIDE + col]     = acc[mt][nt][2] * DESCALE;
                Ls[(row + 8) * LS_STRIDE + col + 1] = acc[mt][nt][3] * DESCALE;
            }
    }
    __syncthreads();

    // --- noisy = logit + noise * softplus(noise_logit) ---
    for (int i = tid; i < MT * EDIM; i += NTHR) {
        const int t = i >> 6, e = i & 63;
        float l  = Ls[t * LS_STRIDE + e];
        float nl = Ls[t * LS_STRIDE + EDIM + e];
        float nz = noise[(size_t)(tokBase + t) * EDIM + e];
        float sp = fmaxf(nl, 0.0f) + log1pf(expf(-fabsf(nl)));
        Ls[t * LS_STRIDE + e] = fmaf(nz, sp, l);
    }
    __syncthreads();

    // --- per-token top-8 (stable: ties keep lower index) ---
    if (tid < MT) {
        const float* row = Ls + tid * LS_STRIDE;
        const float NEG_INF = __int_as_float(0xff800000);
        float best[TOPK]; int bidx[TOPK];
#pragma unroll
        for (int i = 0; i < TOPK; ++i) { best[i] = NEG_INF; bidx[i] = -1; }
        for (int e = 0; e < EDIM; ++e) {
            float v = row[e];
            if (v > best[TOPK - 1]) {
                best[TOPK - 1] = v; bidx[TOPK - 1] = e;
#pragma unroll
                for (int jj = TOPK - 1; jj > 0; --jj) {
                    if (best[jj] > best[jj - 1]) {
                        float tv = best[jj]; best[jj] = best[jj - 1]; best[jj - 1] = tv;
                        int ti = bidx[jj]; bidx[jj] = bidx[jj - 1]; bidx[jj - 1] = ti;
                    }
                }
            }
        }
        float mx = best[0], ssum = 0.0f;
        unsigned long long mask = 0ULL;
#pragma unroll
        for (int i = 0; i < TOPK; ++i) { ssum += expf(best[i] - mx); mask |= 1ULL << bidx[i]; }
        s_max[tid] = mx;
        s_inv[tid] = 1.0f / ssum;
        s_msk[tid] = mask;
        if (write_indices) {
            float* oi = out_indices + (size_t)(tokBase + tid) * TOPK;
#pragma unroll
            for (int i = 0; i < TOPK; ++i) oi[i] = (float)bidx[i];
        }
    }
    __syncthreads();

    // --- sparse softmax write (coalesced) ---
    for (int i = tid; i < MT * EDIM; i += NTHR) {
        const int t = i >> 6, e = i & 63;
        float r = 0.0f;
        if ((s_msk[t] >> e) & 1ULL)
            r = expf(Ls[t * LS_STRIDE + e] - s_max[t]) * s_inv[t];
        out_router[(size_t)(tokBase + t) * EDIM + e] = r;
    }
}

extern "C" void kernel_launch(void* const* d_in, const int* in_sizes, int n_in,
                              void* d_out, int out_size) {
    const float* x  = (const float*)d_in[0];   // (4,4096,2048)
    const float* wr = (const float*)d_in[1];   // (64,2048)
    const float* wn = (const float*)d_in[2];   // (64,2048)
    const float* nz = (const float*)d_in[3];   // (4,4096,64)
    float* out = (float*)d_out;

    const int M = in_sizes[0] / CDIM;          // 16384 tokens
    const int write_idx = (out_size >= M * EDIM + M * TOPK) ? 1 : 0;
    float* out_idx = out + (size_t)M * EDIM;

    cudaFuncSetAttribute(router_mma_kernel,
                         cudaFuncAttributeMaxDynamicSharedMemorySize, SMEM_DYN);
    router_mma_kernel<<<M / MT, NTHR, SMEM_DYN>>>(x, wr, wn, nz, out, out_idx, write_idx);
}

// round 11
// speedup vs baseline: 1.0473x; 1.0473x over previous
#include <cuda_runtime.h>
#include <cuda_fp16.h>
#include <cstdint>

#define CDIM   2048
#define EDIM   64
#define NTOT   128          // 64 route + 64 noise outputs fused in N
#define TOPK   8
#define MT     128          // tokens per CTA
#define KC     64           // K per chunk (4 ks-steps of 16)
#define NCHUNK (CDIM / KC)  // 32
#define NTHR   512          // 8 consumer warps + 8 producer warps

// operand scaling to keep fp16 residuals out of subnormal range
#define XSCALE   16.0f
#define WSCALE   64.0f
#define DESCALE  (1.0f / (XSCALE * WSCALE))

// smem tile rows: 64 halves (128B) padded to 144B (conflict-free ldmatrix)
#define AROW        144
#define TILE_B      (128 * AROW)        // 18432 B per operand tile (A or B, hi or lo)
#define STAGE_B     (4 * TILE_B)        // Ahi, Alo, Bhi, Blo = 73728 B
#define SMEM_DYN    (2 * STAGE_B)       // 147456 B (reused as Ls in epilogue)
#define LS_STRIDE   129                 // 128*129*4 = 66048 B <= STAGE_B (stage-0 only)

// named barriers (id 0 = __syncthreads)
#define BAR_SYNC(id)   asm volatile("bar.sync %0, %1;"   :: "r"(id), "r"(NTHR) : "memory")
#define BAR_ARRIVE(id) asm volatile("bar.arrive %0, %1;" :: "r"(id), "r"(NTHR) : "memory")
#define FULL0 1
#define FULL1 2
#define EMPTY0 3
#define EMPTY1 4

static __device__ __forceinline__ uint32_t smem_u32(const void* p) {
    uint32_t a;
    asm("{ .reg .u64 t; cvta.to.shared.u64 t, %1; cvt.u32.u64 %0, t; }" : "=r"(a) : "l"(p));
    return a;
}
static __device__ __forceinline__ void ldm_x4(uint32_t& r0, uint32_t& r1, uint32_t& r2,
                                              uint32_t& r3, uint32_t addr) {
    asm volatile("ldmatrix.sync.aligned.m8n8.x4.shared.b16 {%0,%1,%2,%3}, [%4];"
                 : "=r"(r0), "=r"(r1), "=r"(r2), "=r"(r3) : "r"(addr));
}
static __device__ __forceinline__ void mma16816(float* c, const uint32_t* a,
                                                const uint32_t* b) {
    asm volatile(
        "mma.sync.aligned.m16n8k16.row.col.f32.f16.f16.f32 "
        "{%0,%1,%2,%3}, {%4,%5,%6,%7}, {%8,%9}, {%0,%1,%2,%3};"
        : "+f"(c[0]), "+f"(c[1]), "+f"(c[2]), "+f"(c[3])
        : "r"(a[0]), "r"(a[1]), "r"(a[2]), "r"(a[3]), "r"(b[0]), "r"(b[1]));
}
static __device__ __forceinline__ uint32_t pack2h(__half a, __half b) {
    __half2 h = __halves2half2(a, b);
    return *reinterpret_cast<uint32_t*>(&h);
}
// Scale, then split into hi/lo fp16 quads and store 8B each.
static __device__ __forceinline__ void cvt_store(char* hi, char* lo, uint32_t off,
                                                 float4 v, float scale) {
    v.x *= scale; v.y *= scale; v.z *= scale; v.w *= scale;
    __half h0 = __float2half_rn(v.x), h1 = __float2half_rn(v.y);
    __half h2 = __float2half_rn(v.z), h3 = __float2half_rn(v.w);
    float r0 = v.x - __half2float(h0), r1 = v.y - __half2float(h1);
    float r2 = v.z - __half2float(h2), r3 = v.w - __half2float(h3);
    uint2 ph = make_uint2(pack2h(h0, h1), pack2h(h2, h3));
    uint2 pl = make_uint2(pack2h(__float2half_rn(r0), __float2half_rn(r1)),
                          pack2h(__float2half_rn(r2), __float2half_rn(r3)));
    *(uint2*)(hi + off) = ph;
    *(uint2*)(lo + off) = pl;
}

__global__ __launch_bounds__(NTHR, 1)
void router_mma_kernel(
    const float* __restrict__ x, const float* __restrict__ w_route,
    const float* __restrict__ w_noise, const float* __restrict__ noise,
    float* __restrict__ out_router, float* __restrict__ out_indices, int write_indices)
{
    extern __shared__ __align__(16) char smem[];
    __shared__ float s_max[MT];
    __shared__ float s_inv[MT];
    __shared__ unsigned long long s_msk[MT];

    const uint32_t sb = smem_u32(smem);
    const int tid = threadIdx.x;
    const int wid = tid >> 5, lane = tid & 31;
    const int tokBase = blockIdx.x * MT;
    const bool is_consumer = (wid < 8);

    float acc[2][8][4];
#pragma unroll
    for (int mt = 0; mt < 2; ++mt)
#pragma unroll
        for (int nt = 0; nt < 8; ++nt)
#pragma unroll
            for (int k = 0; k < 4; ++k) acc[mt][nt][k] = 0.0f;

    if (!is_consumer) {
        // ================= PRODUCER (warps 8..15, 256 threads) =================
        const int ptid = tid - 256;
        for (int c = 0; c < NCHUNK; ++c) {
            const int s = c & 1;
            if (c >= 2) BAR_SYNC(EMPTY0 + s);
            char* stg = smem + s * STAGE_B;
            const int kbase = c * KC;
#pragma unroll
            for (int r = 0; r < 2; ++r) {
                float4 xv[4], wv[4];
#pragma unroll
                for (int i = 0; i < 4; ++i) {
                    const int idx = ptid + 256 * (r * 4 + i);
                    const int row = idx >> 4, q = idx & 15;
                    xv[i] = *(const float4*)(x + (size_t)(tokBase + row) * CDIM
                                             + kbase + q * 4);
                    const float* wsrc = (row < EDIM)
                        ? (w_route + (size_t)row * CDIM)
                        : (w_noise + (size_t)(row - EDIM) * CDIM);
                    wv[i] = *(const float4*)(wsrc + kbase + q * 4);
                }
#pragma unroll
                for (int i = 0; i < 4; ++i) {
                    const int idx = ptid + 256 * (r * 4 + i);
                    const int row = idx >> 4, q = idx & 15;
                    const uint32_t off = (uint32_t)row * AROW + q * 8;
                    cvt_store(stg, stg + TILE_B, off, xv[i], XSCALE);
                    cvt_store(stg + 2 * TILE_B, stg + 3 * TILE_B, off, wv[i], WSCALE);
                }
            }
            BAR_ARRIVE(FULL0 + s);
        }
    } else {
        // ================= CONSUMER (warps 0..7) =================
        const int wr_ = wid >> 1;        // token rows [32*wr_, +32)
        const int wc_ = wid & 1;         // output cols [64*wc_, +64)
        const int j = lane >> 3, rr = lane & 7;
        const int a_off0 = (32 * wr_ + (j & 1) * 8 + rr) * AROW + (j >> 1) * 16;
        const int b_off0 = (64 * wc_ + (j >> 1) * 8 + rr) * AROW + (j & 1) * 16;

        for (int c = 0; c < NCHUNK; ++c) {
            const int s = c & 1;
            BAR_SYNC(FULL0 + s);
            const uint32_t ah_b = sb + s * STAGE_B;
            const uint32_t al_b = ah_b + TILE_B;
            const uint32_t bh_b = ah_b + 2 * TILE_B;
            const uint32_t bl_b = ah_b + 3 * TILE_B;
#pragma unroll
            for (int ks = 0; ks < 4; ++ks) {
                uint32_t ahi[2][4], alo[2][4];
#pragma unroll
                for (int mt = 0; mt < 2; ++mt) {
                    const uint32_t ao = a_off0 + mt * (16 * AROW) + ks * 32;
                    ldm_x4(ahi[mt][0], ahi[mt][1], ahi[mt][2], ahi[mt][3], ah_b + ao);
                    ldm_x4(alo[mt][0], alo[mt][1], alo[mt][2], alo[mt][3], al_b + ao);
                }
#pragma unroll
                for (int nh = 0; nh < 2; ++nh) {
                    uint32_t bhiF[4][2], bloF[4][2];
                    const uint32_t bbase = b_off0 + nh * (32 * AROW) + ks * 32;
#pragma unroll
                    for (int p = 0; p < 2; ++p) {
                        ldm_x4(bhiF[2 * p][0], bhiF[2 * p][1], bhiF[2 * p + 1][0],
                               bhiF[2 * p + 1][1], bh_b + bbase + p * (16 * AROW));
                        ldm_x4(bloF[2 * p][0], bloF[2 * p][1], bloF[2 * p + 1][0],
                               bloF[2 * p + 1][1], bl_b + bbase + p * (16 * AROW));
                    }
                    // per-acc order hihi->hilo->lohi (bitwise-stable vs R9)
#pragma unroll
                    for (int mt = 0; mt < 2; ++mt)
#pragma unroll
                        for (int n4 = 0; n4 < 4; ++n4)
                            mma16816(acc[mt][nh * 4 + n4], ahi[mt], bhiF[n4]);
#pragma unroll
                    for (int mt = 0; mt < 2; ++mt)
#pragma unroll
                        for (int n4 = 0; n4 < 4; ++n4)
                            mma16816(acc[mt][nh * 4 + n4], ahi[mt], bloF[n4]);
#pragma unroll
                    for (int mt = 0; mt < 2; ++mt)
#pragma unroll
                        for (int n4 = 0; n4 < 4; ++n4)
                            mma16816(acc[mt][nh * 4 + n4], alo[mt], bhiF[n4]);
                }
            }
            BAR_ARRIVE(EMPTY0 + s);
        }

        // accumulators -> Ls[token][output] (stage-0 region; all consumers are
        // past chunk 30's reads of stage 0; chunk 31 reads stage 1 only)
        float* Ls = (float*)smem;
        const int r0 = 32 * wr_ + (lane >> 2);
        const int c0 = 64 * wc_ + 2 * (lane & 3);
#pragma unroll
        for (int mt = 0; mt < 2; ++mt)
#pragma unroll
            for (int nt = 0; nt < 8; ++nt) {
                const int row = r0 + 16 * mt;
                const int col = c0 + 8 * nt;
                Ls[row * LS_STRIDE + col]           = acc[mt][nt][0] * DESCALE;
                Ls[row * LS_STRIDE + col + 1]       = acc[mt][nt][1] * DESCALE;
                Ls[(row + 8) * LS_STRIDE + col]     = acc[mt][nt][2] * DESCALE;
                Ls[(row + 8) * LS_STRIDE + col + 1] = acc[mt][nt][3] * DESCALE;
            }
    }
    __syncthreads();

    // --- noisy = logit + noise * softplus(noise_logit) ---
    float* Ls = (float*)smem;
    for (int i = tid; i < MT * EDIM; i += NTHR) {
        const int t = i >> 6, e = i & 63;
        float l  = Ls[t * LS_STRIDE + e];
        float nl = Ls[t * LS_STRIDE + EDIM + e];
        float nz = noise[(size_t)(tokBase + t) * EDIM + e];
        float sp = fmaxf(nl, 0.0f) + log1pf(expf(-fabsf(nl)));
        Ls[t * LS_STRIDE + e] = fmaf(nz, sp, l);
    }
    __syncthreads();

    // --- per-token top-8 (stable: ties keep lower index) ---
    if (tid < MT) {
        const float* row = Ls + tid * LS_STRIDE;
        const float NEG_INF = __int_as_float(0xff800000);
        float best[TOPK]; int bidx[TOPK];
#pragma unroll
        for (int i = 0; i < TOPK; ++i) { best[i] = NEG_INF; bidx[i] = -1; }
        for (int e = 0; e < EDIM; ++e) {
            float v = row[e];
            if (v > best[TOPK - 1]) {
                best[TOPK - 1] = v; bidx[TOPK - 1] = e;
#pragma unroll
                for (int jj = TOPK - 1; jj > 0; --jj) {
                    if (best[jj] > best[jj - 1]) {
                        float tv = best[jj]; best[jj] = best[jj - 1]; best[jj - 1] = tv;
                        int ti = bidx[jj]; bidx[jj] = bidx[jj - 1]; bidx[jj - 1] = ti;
                    }
                }
            }
        }
        float mx = best[0], ssum = 0.0f;
        unsigned long long mask = 0ULL;
#pragma unroll
        for (int i = 0; i < TOPK; ++i) { ssum += expf(best[i] - mx); mask |= 1ULL << bidx[i]; }
        s_max[tid] = mx;
        s_inv[tid] = 1.0f / ssum;
        s_msk[tid] = mask;
        if (write_indices) {
            float* oi = out_indices + (size_t)(tokBase + tid) * TOPK;
#pragma unroll
            for (int i = 0; i < TOPK; ++i) oi[i] = (float)bidx[i];
        }
    }
    __syncthreads();

    // --- sparse softmax write (coalesced) ---
    for (int i = tid; i < MT * EDIM; i += NTHR) {
        const int t = i >> 6, e = i & 63;
        float r = 0.0f;
        if ((s_msk[t] >> e) & 1ULL)
            r = expf(Ls[t * LS_STRIDE + e] - s_max[t]) * s_inv[t];
        out_router[(size_t)(tokBase + t) * EDIM + e] = r;
    }
}

extern "C" void kernel_launch(void* const* d_in, const int* in_sizes, int n_in,
                              void* d_out, int out_size) {
    const float* x  = (const float*)d_in[0];   // (4,4096,2048)
    const float* wr = (const float*)d_in[1];   // (64,2048)
    const float* wn = (const float*)d_in[2];   // (64,2048)
    const float* nz = (const float*)d_in[3];   // (4,4096,64)
    float* out = (float*)d_out;

    const int M = in_sizes[0] / CDIM;          // 16384 tokens
    const int write_idx = (out_size >= M * EDIM + M * TOPK) ? 1 : 0;
    float* out_idx = out + (size_t)M * EDIM;

    cudaFuncSetAttribute(router_mma_kernel,
                         cudaFuncAttributeMaxDynamicSharedMemorySize, SMEM_DYN);
    router_mma_kernel<<<M / MT, NTHR, SMEM_DYN>>>(x, wr, wn, nz, out, out_idx, write_idx);
}